// round 3
// baseline (speedup 1.0000x reference)
#include <cuda_runtime.h>
#include <math.h>

#define E_MAX 160000
#define N_MAX 10000

// scratch (static __device__ -> allowed, no allocations)
__device__ float g_mix[(size_t)E_MAX * 256];   // per-edge radial MLP output
__device__ float g_y[(size_t)E_MAX * 16];      // per-edge Y_1(3),Y_2(5),Y_3(7),pad
__device__ int   g_count[N_MAX + 1];
__device__ int   g_start[N_MAX + 2];
__device__ int   g_cursor[N_MAX + 1];
__device__ int   g_esort[E_MAX];

// ---------------- packed f32x2 helpers (exact fp32, 2 FMAs / issue) ----------
__device__ __forceinline__ unsigned long long splat2(float x) {
    unsigned long long r;
    unsigned u = __float_as_uint(x);
    asm("mov.b64 %0, {%1, %1};" : "=l"(r) : "r"(u));
    return r;
}
__device__ __forceinline__ void fma2(unsigned long long& acc,
                                     unsigned long long a, unsigned long long b) {
    asm("fma.rn.f32x2 %0, %1, %2, %0;" : "+l"(acc) : "l"(a), "l"(b));
}
__device__ __forceinline__ float2 unpack2(unsigned long long v) {
    unsigned lo, hi;
    asm("mov.b64 {%0, %1}, %2;" : "=r"(lo), "=r"(hi) : "l"(v));
    return make_float2(__uint_as_float(lo), __uint_as_float(hi));
}
__device__ __forceinline__ float silu(float v) {
    return v * (1.0f / (1.0f + __expf(-v)));
}

// ---------------------------------------------------------------- zero counts
__global__ void k_zero(int n) {
    int i = blockIdx.x * blockDim.x + threadIdx.x;
    if (i <= n) g_count[i] = 0;
}

// ------------------------------------------- spherical harmonics + histogram
__global__ void k_y_hist(const float* __restrict__ vectors,
                         const int* __restrict__ receivers, int E) {
    int e = blockIdx.x * blockDim.x + threadIdx.x;
    if (e >= E) return;
    float x = vectors[3 * e + 0];
    float y = vectors[3 * e + 1];
    float z = vectors[3 * e + 2];
    float n2 = x * x + y * y + z * z;
    float inv = 1.0f / (sqrtf(n2) + 1e-12f);
    x *= inv; y *= inv; z *= inv;

    const float s3  = 1.7320508075688772f;
    const float s5  = 2.23606797749979f;
    const float s15 = 3.872983346207417f;
    const float c33 = 2.091650066335189f;
    const float c32 = 10.246950765959598f;
    const float c31 = 1.6201851746019651f;
    const float c30 = 1.3228756555322954f;

    float yv[16];
    yv[0] = s3 * y;  yv[1] = s3 * z;  yv[2] = s3 * x;
    yv[3] = s15 * x * y;
    yv[4] = s15 * y * z;
    yv[5] = 0.5f * s5 * (3.0f * z * z - 1.0f);
    yv[6] = s15 * x * z;
    yv[7] = 0.5f * s15 * (x * x - y * y);
    yv[8]  = c33 * y * (3.0f * x * x - y * y);
    yv[9]  = c32 * x * y * z;
    yv[10] = c31 * y * (5.0f * z * z - 1.0f);
    yv[11] = c30 * z * (5.0f * z * z - 3.0f);
    yv[12] = c31 * x * (5.0f * z * z - 1.0f);
    yv[13] = 0.5f * c32 * z * (x * x - y * y);
    yv[14] = c33 * x * (x * x - 3.0f * y * y);
    yv[15] = 1.0f;

    float4* o = (float4*)(g_y + (size_t)e * 16);
    o[0] = make_float4(yv[0], yv[1], yv[2], yv[3]);
    o[1] = make_float4(yv[4], yv[5], yv[6], yv[7]);
    o[2] = make_float4(yv[8], yv[9], yv[10], yv[11]);
    o[3] = make_float4(yv[12], yv[13], yv[14], yv[15]);

    atomicAdd(&g_count[receivers[e]], 1);
}

// ---------------------------------------------------------------- CSR scan
__global__ void k_scan(int n, int E) {
    __shared__ int sums[1024];
    int t = threadIdx.x;
    int chunk = (n + 1023) >> 10;
    int b = t * chunk;
    int eidx = min(b + chunk, n);
    int s = 0;
    for (int i = b; i < eidx; i++) s += g_count[i];
    sums[t] = s;
    __syncthreads();
    for (int off = 1; off < 1024; off <<= 1) {
        int v = (t >= off) ? sums[t - off] : 0;
        __syncthreads();
        sums[t] += v;
        __syncthreads();
    }
    int pre = (t > 0) ? sums[t - 1] : 0;
    for (int i = b; i < eidx; i++) {
        g_start[i]  = pre;
        g_cursor[i] = pre;
        pre += g_count[i];
    }
    if (t == 1023) g_start[n] = E;
}

// ---------------------------------------------------------------- scatter
__global__ void k_scatter(const int* __restrict__ receivers, int E) {
    int e = blockIdx.x * blockDim.x + threadIdx.x;
    if (e >= E) return;
    int p = atomicAdd(&g_cursor[receivers[e]], 1);
    g_esort[p] = e;
}

// ---------------------------------------------------------------- radial MLP
// 2 edges per thread: weight LDS.128 broadcasts amortized over 2 edges.
// Full-width 64-out accumulation (32 u64 per edge) -> h single-buffered in
// shared, overwritten in place. f32x2 packed FMAs throughout.

__device__ __forceinline__ void layer64(const float* __restrict__ Ws, int wstride, int j0,
                                        const float* __restrict__ h0,
                                        const float* __restrict__ h1, int lane,
                                        unsigned long long* acc0,
                                        unsigned long long* acc1) {
    #pragma unroll
    for (int q = 0; q < 32; q++) { acc0[q] = 0ULL; acc1[q] = 0ULL; }
    #pragma unroll 4
    for (int k = 0; k < 64; k++) {
        unsigned long long a = splat2(h0[k ^ lane]);
        unsigned long long b = splat2(h1[k ^ lane]);
        const ulonglong2* wp = (const ulonglong2*)(Ws + k * wstride + j0);
        #pragma unroll
        for (int q = 0; q < 16; q++) {
            ulonglong2 w = wp[q];
            fma2(acc0[2 * q],     a, w.x);
            fma2(acc0[2 * q + 1], a, w.y);
            fma2(acc1[2 * q],     b, w.x);
            fma2(acc1[2 * q + 1], b, w.y);
        }
    }
}

__device__ __forceinline__ void silu_store(float* __restrict__ h,
                                           const unsigned long long* acc, int lane) {
    #pragma unroll
    for (int q = 0; q < 32; q++) {
        float2 v = unpack2(acc[q]);
        h[(2 * q)     ^ lane] = silu(v.x);
        h[(2 * q + 1) ^ lane] = silu(v.y);
    }
}

__global__ void __launch_bounds__(256, 1)
k_mlp(const float* __restrict__ radial,
      const float* __restrict__ w1, const float* __restrict__ w2,
      const float* __restrict__ w3, const float* __restrict__ w4, int E) {
    extern __shared__ float smem[];
    float* w1s = smem;                 // 512
    float* w2s = w1s + 512;            // 4096
    float* w3s = w2s + 4096;           // 4096
    float* w4s = w3s + 4096;           // 16384
    float* hS  = w4s + 16384;          // 512*64 floats (single-buffered)

    int tid = threadIdx.x;
    for (int i = tid; i < 512;   i += 256) w1s[i] = w1[i] * 0.35355339059327379f;
    for (int i = tid; i < 4096;  i += 256) w2s[i] = w2[i] * 0.125f;
    for (int i = tid; i < 4096;  i += 256) w3s[i] = w3[i] * 0.125f;
    for (int i = tid; i < 16384; i += 256) w4s[i] = w4[i] * 0.125f;
    __syncthreads();

    int lane = tid & 31;
    int base = blockIdx.x * 512;
    int e0 = base + tid;
    int e1 = base + 256 + tid;
    int eA = min(e0, E - 1);
    int eB = min(e1, E - 1);

    float* h0 = hS + tid * 64;          // private slices, xor-swizzled by lane
    float* h1 = hS + (256 + tid) * 64;

    unsigned long long acc0[32], acc1[32];

    // ---- layer 1: 8 -> 64
    {
        float r0[8], r1[8];
        const float4* rp0 = (const float4*)(radial + (size_t)eA * 8);
        const float4* rp1 = (const float4*)(radial + (size_t)eB * 8);
        float4 a0 = __ldg(rp0), a1 = __ldg(rp0 + 1);
        float4 b0 = __ldg(rp1), b1 = __ldg(rp1 + 1);
        r0[0] = a0.x; r0[1] = a0.y; r0[2] = a0.z; r0[3] = a0.w;
        r0[4] = a1.x; r0[5] = a1.y; r0[6] = a1.z; r0[7] = a1.w;
        r1[0] = b0.x; r1[1] = b0.y; r1[2] = b0.z; r1[3] = b0.w;
        r1[4] = b1.x; r1[5] = b1.y; r1[6] = b1.z; r1[7] = b1.w;

        #pragma unroll
        for (int q = 0; q < 32; q++) { acc0[q] = 0ULL; acc1[q] = 0ULL; }
        #pragma unroll
        for (int k = 0; k < 8; k++) {
            unsigned long long a = splat2(r0[k]);
            unsigned long long b = splat2(r1[k]);
            const ulonglong2* wp = (const ulonglong2*)(w1s + k * 64);
            #pragma unroll
            for (int q = 0; q < 16; q++) {
                ulonglong2 w = wp[q];
                fma2(acc0[2 * q],     a, w.x);
                fma2(acc0[2 * q + 1], a, w.y);
                fma2(acc1[2 * q],     b, w.x);
                fma2(acc1[2 * q + 1], b, w.y);
            }
        }
        silu_store(h0, acc0, lane);
        silu_store(h1, acc1, lane);
    }

    // ---- layer 2: 64 -> 64 (in place)
    layer64(w2s, 64, 0, h0, h1, lane, acc0, acc1);
    silu_store(h0, acc0, lane);
    silu_store(h1, acc1, lane);

    // ---- layer 3: 64 -> 64 (in place)
    layer64(w3s, 64, 0, h0, h1, lane, acc0, acc1);
    silu_store(h0, acc0, lane);
    silu_store(h1, acc1, lane);

    // ---- layer 4: 64 -> 256, 4 tiles of 64 outputs
    float* mo0 = g_mix + (size_t)e0 * 256;
    float* mo1 = g_mix + (size_t)e1 * 256;
    #pragma unroll 1
    for (int t = 0; t < 4; t++) {
        int j0 = t * 64;
        layer64(w4s, 256, j0, h0, h1, lane, acc0, acc1);
        // packed u64 pairs are exactly two consecutive floats -> direct stores
        if (e0 < E) {
            ulonglong2* op = (ulonglong2*)(mo0 + j0);
            #pragma unroll
            for (int q = 0; q < 16; q++)
                op[q] = make_ulonglong2(acc0[2 * q], acc0[2 * q + 1]);
        }
        if (e1 < E) {
            ulonglong2* op = (ulonglong2*)(mo1 + j0);
            #pragma unroll
            for (int q = 0; q < 16; q++)
                op[q] = make_ulonglong2(acc1[2 * q], acc1[2 * q + 1]);
        }
    }
}

// --------------------------------------------------- gather-side reduction
__global__ void __launch_bounds__(256)
k_out(const float* __restrict__ node_feats, const int* __restrict__ senders,
      float* __restrict__ out, int N) {
    __shared__ float red[8 * 1024];
    int node = blockIdx.x;
    int tid = threadIdx.x;
    int w = tid >> 5, lane = tid & 31;
    int beg = g_start[node], end = g_start[node + 1];

    float acc[32];
    #pragma unroll
    for (int i = 0; i < 32; i++) acc[i] = 0.0f;

    for (int p = beg + w; p < end; p += 8) {
        int e = g_esort[p];
        int snd = senders[e];
        const float* mixp = g_mix + (size_t)e * 256;
        const float4* yp = (const float4*)(g_y + (size_t)e * 16);
        float4 ya = __ldg(yp), yb = __ldg(yp + 1), yc = __ldg(yp + 2), yd = __ldg(yp + 3);
        float yv[15] = {ya.x, ya.y, ya.z, ya.w, yb.x, yb.y, yb.z, yb.w,
                        yc.x, yc.y, yc.z, yc.w, yd.x, yd.y, yd.z};
        #pragma unroll
        for (int h = 0; h < 2; h++) {
            int c = lane + 32 * h;
            float s   = __ldg(node_feats + (size_t)snd * 64 + c);
            float sm0 = s * __ldg(mixp + c);
            float sm1 = s * __ldg(mixp + 64 + c);
            float sm2 = s * __ldg(mixp + 128 + c);
            float sm3 = s * __ldg(mixp + 192 + c);
            float* a = acc + 16 * h;
            a[0] += sm0;
            a[1] = fmaf(sm1, yv[0], a[1]);
            a[2] = fmaf(sm1, yv[1], a[2]);
            a[3] = fmaf(sm1, yv[2], a[3]);
            #pragma unroll
            for (int m = 0; m < 5; m++) a[4 + m] = fmaf(sm2, yv[3 + m], a[4 + m]);
            #pragma unroll
            for (int m = 0; m < 7; m++) a[9 + m] = fmaf(sm3, yv[8 + m], a[9 + m]);
        }
    }

    float* rw = red + w * 1024;
    #pragma unroll
    for (int h = 0; h < 2; h++) {
        int c = lane + 32 * h;
        float* a = acc + 16 * h;
        rw[c] = a[0];
        rw[64 + c * 3 + 0] = a[1];
        rw[64 + c * 3 + 1] = a[2];
        rw[64 + c * 3 + 2] = a[3];
        #pragma unroll
        for (int m = 0; m < 5; m++) rw[256 + c * 5 + m] = a[4 + m];
        #pragma unroll
        for (int m = 0; m < 7; m++) rw[576 + c * 7 + m] = a[9 + m];
    }
    __syncthreads();

    float* outp = out + (size_t)node * 1024;
    #pragma unroll
    for (int i = 0; i < 4; i++) {
        int o = tid + 256 * i;
        float sum = 0.0f;
        #pragma unroll
        for (int ww = 0; ww < 8; ww++) sum += red[ww * 1024 + o];
        outp[o] = sum * 0.25f;   // 1/sqrt(16)
    }
}

// ---------------------------------------------------------------- launcher
extern "C" void kernel_launch(void* const* d_in, const int* in_sizes, int n_in,
                              void* d_out, int out_size) {
    const float* vectors    = (const float*)d_in[0];
    const float* node_feats = (const float*)d_in[1];
    const float* radial     = (const float*)d_in[2];
    const float* w1         = (const float*)d_in[3];
    const float* w2         = (const float*)d_in[4];
    const float* w3         = (const float*)d_in[5];
    const float* w4         = (const float*)d_in[6];
    const int*   senders    = (const int*)d_in[7];
    const int*   receivers  = (const int*)d_in[8];

    int E = in_sizes[7];
    int N = in_sizes[1] / 64;

    const int SMEM_MLP = (512 + 4096 + 4096 + 16384 + 512 * 64) * 4; // 231424
    cudaFuncSetAttribute(k_mlp, cudaFuncAttributeMaxDynamicSharedMemorySize, SMEM_MLP);

    int gE = (E + 255) / 256;
    int gM = (E + 511) / 512;
    k_zero<<<(N + 1 + 255) / 256, 256>>>(N);
    k_y_hist<<<gE, 256>>>(vectors, receivers, E);
    k_scan<<<1, 1024>>>(N, E);
    k_mlp<<<gM, 256, SMEM_MLP>>>(radial, w1, w2, w3, w4, E);
    k_scatter<<<gE, 256>>>(receivers, E);
    k_out<<<N, 256>>>(node_feats, senders, (float*)d_out, N);
}

// round 4
// speedup vs baseline: 1.1391x; 1.1391x over previous
#include <cuda_runtime.h>
#include <math.h>

#define E_MAX 160000
#define N_MAX 10000

// scratch (static __device__ -> allowed, no allocations)
__device__ float g_mix[(size_t)E_MAX * 256];   // per-edge radial MLP output
__device__ float g_hA[(size_t)64 * E_MAX];     // transposed activations [k][e]
__device__ float g_hB[(size_t)64 * E_MAX];
__device__ float g_y[(size_t)E_MAX * 16];      // per-edge Y_1(3),Y_2(5),Y_3(7),pad
__device__ int   g_count[N_MAX + 1];
__device__ int   g_start[N_MAX + 2];
__device__ int   g_cursor[N_MAX + 1];
__device__ int   g_esort[E_MAX];

// ---------------- packed f32x2 helpers (exact fp32, 2 FMAs / issue) ----------
__device__ __forceinline__ unsigned long long splat2(float x) {
    unsigned long long r;
    unsigned u = __float_as_uint(x);
    asm("mov.b64 %0, {%1, %1};" : "=l"(r) : "r"(u));
    return r;
}
__device__ __forceinline__ void fma2(unsigned long long& acc,
                                     unsigned long long a, unsigned long long b) {
    asm("fma.rn.f32x2 %0, %1, %2, %0;" : "+l"(acc) : "l"(a), "l"(b));
}
__device__ __forceinline__ float2 unpack2(unsigned long long v) {
    unsigned lo, hi;
    asm("mov.b64 {%0, %1}, %2;" : "=r"(lo), "=r"(hi) : "l"(v));
    return make_float2(__uint_as_float(lo), __uint_as_float(hi));
}
__device__ __forceinline__ float silu(float v) {
    return v * (1.0f / (1.0f + __expf(-v)));
}

// ---------------------------------------------------------------- zero counts
__global__ void k_zero(int n) {
    int i = blockIdx.x * blockDim.x + threadIdx.x;
    if (i <= n) g_count[i] = 0;
}

// ------------------------------------------- spherical harmonics + histogram
__global__ void k_y_hist(const float* __restrict__ vectors,
                         const int* __restrict__ receivers, int E) {
    int e = blockIdx.x * blockDim.x + threadIdx.x;
    if (e >= E) return;
    float x = vectors[3 * e + 0];
    float y = vectors[3 * e + 1];
    float z = vectors[3 * e + 2];
    float n2 = x * x + y * y + z * z;
    float inv = 1.0f / (sqrtf(n2) + 1e-12f);
    x *= inv; y *= inv; z *= inv;

    const float s3  = 1.7320508075688772f;
    const float s5  = 2.23606797749979f;
    const float s15 = 3.872983346207417f;
    const float c33 = 2.091650066335189f;
    const float c32 = 10.246950765959598f;
    const float c31 = 1.6201851746019651f;
    const float c30 = 1.3228756555322954f;

    float yv[16];
    yv[0] = s3 * y;  yv[1] = s3 * z;  yv[2] = s3 * x;
    yv[3] = s15 * x * y;
    yv[4] = s15 * y * z;
    yv[5] = 0.5f * s5 * (3.0f * z * z - 1.0f);
    yv[6] = s15 * x * z;
    yv[7] = 0.5f * s15 * (x * x - y * y);
    yv[8]  = c33 * y * (3.0f * x * x - y * y);
    yv[9]  = c32 * x * y * z;
    yv[10] = c31 * y * (5.0f * z * z - 1.0f);
    yv[11] = c30 * z * (5.0f * z * z - 3.0f);
    yv[12] = c31 * x * (5.0f * z * z - 1.0f);
    yv[13] = 0.5f * c32 * z * (x * x - y * y);
    yv[14] = c33 * x * (x * x - 3.0f * y * y);
    yv[15] = 1.0f;

    float4* o = (float4*)(g_y + (size_t)e * 16);
    o[0] = make_float4(yv[0], yv[1], yv[2], yv[3]);
    o[1] = make_float4(yv[4], yv[5], yv[6], yv[7]);
    o[2] = make_float4(yv[8], yv[9], yv[10], yv[11]);
    o[3] = make_float4(yv[12], yv[13], yv[14], yv[15]);

    atomicAdd(&g_count[receivers[e]], 1);
}

// ---------------------------------------------------------------- CSR scan
__global__ void k_scan(int n, int E) {
    __shared__ int sums[1024];
    int t = threadIdx.x;
    int chunk = (n + 1023) >> 10;
    int b = t * chunk;
    int eidx = min(b + chunk, n);
    int s = 0;
    for (int i = b; i < eidx; i++) s += g_count[i];
    sums[t] = s;
    __syncthreads();
    for (int off = 1; off < 1024; off <<= 1) {
        int v = (t >= off) ? sums[t - off] : 0;
        __syncthreads();
        sums[t] += v;
        __syncthreads();
    }
    int pre = (t > 0) ? sums[t - 1] : 0;
    for (int i = b; i < eidx; i++) {
        g_start[i]  = pre;
        g_cursor[i] = pre;
        pre += g_count[i];
    }
    if (t == 1023) g_start[n] = E;
}

// ---------------------------------------------------------------- scatter
__global__ void k_scatter(const int* __restrict__ receivers, int E) {
    int e = blockIdx.x * blockDim.x + threadIdx.x;
    if (e >= E) return;
    int p = atomicAdd(&g_cursor[receivers[e]], 1);
    g_esort[p] = e;
}

// ---------------------------------------------------------------- radial MLP
// h lives in transposed GLOBAL scratch g_h[k][e] (L2-resident, coalesced,
// same-thread RAW -> no sync). Shared holds only the 100KB weights ->
// 2 blocks x 256 thr = 16 warps/SM. k-outer / j-inner-64 (32 u64 acc).

// one 64-wide output pass: out[j0..j0+63] = sum_k in_g[k][e] * Ws[k][wstride]+j0
__device__ __forceinline__ void passG(const float* __restrict__ in_g, int e,
                                      const float* __restrict__ Ws, int wstride, int j0,
                                      unsigned long long* __restrict__ acc) {
    #pragma unroll
    for (int q = 0; q < 32; q++) acc[q] = 0ULL;
    #pragma unroll 4
    for (int k = 0; k < 64; k++) {
        unsigned long long a = splat2(__ldg(in_g + (size_t)k * E_MAX + e));
        const ulonglong2* wp = (const ulonglong2*)(Ws + k * wstride + j0);
        #pragma unroll
        for (int q = 0; q < 16; q++) {
            ulonglong2 w = wp[q];
            fma2(acc[2 * q],     a, w.x);
            fma2(acc[2 * q + 1], a, w.y);
        }
    }
}

__device__ __forceinline__ void silu_store_g(float* __restrict__ out_g, int e,
                                             const unsigned long long* __restrict__ acc) {
    #pragma unroll
    for (int q = 0; q < 32; q++) {
        float2 v = unpack2(acc[q]);
        out_g[(size_t)(2 * q)     * E_MAX + e] = silu(v.x);
        out_g[(size_t)(2 * q + 1) * E_MAX + e] = silu(v.y);
    }
}

__global__ void __launch_bounds__(256, 2)
k_mlp(const float* __restrict__ radial,
      const float* __restrict__ w1, const float* __restrict__ w2,
      const float* __restrict__ w3, const float* __restrict__ w4, int E) {
    extern __shared__ float smem[];
    float* w1s = smem;                 // 512
    float* w2s = w1s + 512;            // 4096
    float* w3s = w2s + 4096;           // 4096
    float* w4s = w3s + 4096;           // 16384  (total 25088 floats = 100.4KB)

    int tid = threadIdx.x;
    for (int i = tid; i < 512;   i += 256) w1s[i] = w1[i] * 0.35355339059327379f;
    for (int i = tid; i < 4096;  i += 256) w2s[i] = w2[i] * 0.125f;
    for (int i = tid; i < 4096;  i += 256) w3s[i] = w3[i] * 0.125f;
    for (int i = tid; i < 16384; i += 256) w4s[i] = w4[i] * 0.125f;
    __syncthreads();

    int e = blockIdx.x * 256 + tid;
    if (e >= E) return;

    unsigned long long acc[32];

    // ---- layer 1: 8 -> 64 -> g_hA
    {
        const float4* rp = (const float4*)(radial + (size_t)e * 8);
        float4 a0 = __ldg(rp), a1 = __ldg(rp + 1);
        float r[8] = {a0.x, a0.y, a0.z, a0.w, a1.x, a1.y, a1.z, a1.w};
        #pragma unroll
        for (int q = 0; q < 32; q++) acc[q] = 0ULL;
        #pragma unroll
        for (int k = 0; k < 8; k++) {
            unsigned long long a = splat2(r[k]);
            const ulonglong2* wp = (const ulonglong2*)(w1s + k * 64);
            #pragma unroll
            for (int q = 0; q < 16; q++) {
                ulonglong2 w = wp[q];
                fma2(acc[2 * q],     a, w.x);
                fma2(acc[2 * q + 1], a, w.y);
            }
        }
        silu_store_g(g_hA, e, acc);
    }

    // ---- layer 2: g_hA -> g_hB
    passG(g_hA, e, w2s, 64, 0, acc);
    silu_store_g(g_hB, e, acc);

    // ---- layer 3: g_hB -> g_hA
    passG(g_hB, e, w3s, 64, 0, acc);
    silu_store_g(g_hA, e, acc);

    // ---- layer 4: g_hA -> g_mix (4 passes of 64 outputs, no activation)
    float* mo = g_mix + (size_t)e * 256;
    #pragma unroll 1
    for (int p = 0; p < 4; p++) {
        int j0 = p * 64;
        passG(g_hA, e, w4s, 256, j0, acc);
        // packed u64 pairs are exactly two consecutive floats -> direct stores
        ulonglong2* op = (ulonglong2*)(mo + j0);
        #pragma unroll
        for (int q = 0; q < 16; q++)
            op[q] = make_ulonglong2(acc[2 * q], acc[2 * q + 1]);
    }
}

// --------------------------------------------------- gather-side reduction
__global__ void __launch_bounds__(256)
k_out(const float* __restrict__ node_feats, const int* __restrict__ senders,
      float* __restrict__ out, int N) {
    __shared__ float red[8 * 1024];
    int node = blockIdx.x;
    int tid = threadIdx.x;
    int w = tid >> 5, lane = tid & 31;
    int beg = g_start[node], end = g_start[node + 1];

    float acc[32];
    #pragma unroll
    for (int i = 0; i < 32; i++) acc[i] = 0.0f;

    for (int p = beg + w; p < end; p += 8) {
        int e = g_esort[p];
        int snd = senders[e];
        const float* mixp = g_mix + (size_t)e * 256;
        const float4* yp = (const float4*)(g_y + (size_t)e * 16);
        float4 ya = __ldg(yp), yb = __ldg(yp + 1), yc = __ldg(yp + 2), yd = __ldg(yp + 3);
        float yv[15] = {ya.x, ya.y, ya.z, ya.w, yb.x, yb.y, yb.z, yb.w,
                        yc.x, yc.y, yc.z, yc.w, yd.x, yd.y, yd.z};
        #pragma unroll
        for (int h = 0; h < 2; h++) {
            int c = lane + 32 * h;
            float s   = __ldg(node_feats + (size_t)snd * 64 + c);
            float sm0 = s * __ldg(mixp + c);
            float sm1 = s * __ldg(mixp + 64 + c);
            float sm2 = s * __ldg(mixp + 128 + c);
            float sm3 = s * __ldg(mixp + 192 + c);
            float* a = acc + 16 * h;
            a[0] += sm0;
            a[1] = fmaf(sm1, yv[0], a[1]);
            a[2] = fmaf(sm1, yv[1], a[2]);
            a[3] = fmaf(sm1, yv[2], a[3]);
            #pragma unroll
            for (int m = 0; m < 5; m++) a[4 + m] = fmaf(sm2, yv[3 + m], a[4 + m]);
            #pragma unroll
            for (int m = 0; m < 7; m++) a[9 + m] = fmaf(sm3, yv[8 + m], a[9 + m]);
        }
    }

    float* rw = red + w * 1024;
    #pragma unroll
    for (int h = 0; h < 2; h++) {
        int c = lane + 32 * h;
        float* a = acc + 16 * h;
        rw[c] = a[0];
        rw[64 + c * 3 + 0] = a[1];
        rw[64 + c * 3 + 1] = a[2];
        rw[64 + c * 3 + 2] = a[3];
        #pragma unroll
        for (int m = 0; m < 5; m++) rw[256 + c * 5 + m] = a[4 + m];
        #pragma unroll
        for (int m = 0; m < 7; m++) rw[576 + c * 7 + m] = a[9 + m];
    }
    __syncthreads();

    float* outp = out + (size_t)node * 1024;
    #pragma unroll
    for (int i = 0; i < 4; i++) {
        int o = tid + 256 * i;
        float sum = 0.0f;
        #pragma unroll
        for (int ww = 0; ww < 8; ww++) sum += red[ww * 1024 + o];
        outp[o] = sum * 0.25f;   // 1/sqrt(16)
    }
}

// ---------------------------------------------------------------- launcher
extern "C" void kernel_launch(void* const* d_in, const int* in_sizes, int n_in,
                              void* d_out, int out_size) {
    const float* vectors    = (const float*)d_in[0];
    const float* node_feats = (const float*)d_in[1];
    const float* radial     = (const float*)d_in[2];
    const float* w1         = (const float*)d_in[3];
    const float* w2         = (const float*)d_in[4];
    const float* w3         = (const float*)d_in[5];
    const float* w4         = (const float*)d_in[6];
    const int*   senders    = (const int*)d_in[7];
    const int*   receivers  = (const int*)d_in[8];

    int E = in_sizes[7];
    int N = in_sizes[1] / 64;

    const int SMEM_MLP = 25088 * 4;   // weights only: 100,352 B -> 2 blocks/SM
    cudaFuncSetAttribute(k_mlp, cudaFuncAttributeMaxDynamicSharedMemorySize, SMEM_MLP);

    int gE = (E + 255) / 256;
    k_zero<<<(N + 1 + 255) / 256, 256>>>(N);
    k_y_hist<<<gE, 256>>>(vectors, receivers, E);
    k_scan<<<1, 1024>>>(N, E);
    k_mlp<<<gE, 256, SMEM_MLP>>>(radial, w1, w2, w3, w4, E);
    k_scatter<<<gE, 256>>>(receivers, E);
    k_out<<<N, 256>>>(node_feats, senders, (float*)d_out, N);
}

// round 5
// speedup vs baseline: 1.1440x; 1.0043x over previous
#include <cuda_runtime.h>
#include <math.h>

#define E_MAX 160000
#define N_MAX 10000

// scratch (static __device__ -> allowed, no allocations)
__device__ float g_mix[(size_t)E_MAX * 256];   // per-edge radial MLP output
__device__ float g_hA[(size_t)64 * E_MAX];     // transposed activations [k][e]
__device__ float g_hB[(size_t)64 * E_MAX];
__device__ float g_y[(size_t)E_MAX * 16];      // per-edge Y_1(3),Y_2(5),Y_3(7),pad
__device__ int   g_count[N_MAX + 1];
__device__ int   g_start[N_MAX + 2];
__device__ int   g_cursor[N_MAX + 1];
__device__ int   g_esort[E_MAX];

// ---------------- packed f32x2 helpers (exact fp32, 2 FMAs / issue) ----------
__device__ __forceinline__ unsigned long long splat2(float x) {
    unsigned long long r;
    unsigned u = __float_as_uint(x);
    asm("mov.b64 %0, {%1, %1};" : "=l"(r) : "r"(u));
    return r;
}
__device__ __forceinline__ void fma2(unsigned long long& acc,
                                     unsigned long long a, unsigned long long b) {
    asm("fma.rn.f32x2 %0, %1, %2, %0;" : "+l"(acc) : "l"(a), "l"(b));
}
__device__ __forceinline__ float2 unpack2(unsigned long long v) {
    unsigned lo, hi;
    asm("mov.b64 {%0, %1}, %2;" : "=r"(lo), "=r"(hi) : "l"(v));
    return make_float2(__uint_as_float(lo), __uint_as_float(hi));
}
__device__ __forceinline__ float silu(float v) {
    return v * (1.0f / (1.0f + __expf(-v)));
}

// ---------------------------------------------------------------- zero counts
__global__ void k_zero(int n) {
    int i = blockIdx.x * blockDim.x + threadIdx.x;
    if (i <= n) g_count[i] = 0;
}

// ------------------------------------------- spherical harmonics + histogram
__global__ void k_y_hist(const float* __restrict__ vectors,
                         const int* __restrict__ receivers, int E) {
    int e = blockIdx.x * blockDim.x + threadIdx.x;
    if (e >= E) return;
    float x = vectors[3 * e + 0];
    float y = vectors[3 * e + 1];
    float z = vectors[3 * e + 2];
    float n2 = x * x + y * y + z * z;
    float inv = 1.0f / (sqrtf(n2) + 1e-12f);
    x *= inv; y *= inv; z *= inv;

    const float s3  = 1.7320508075688772f;
    const float s5  = 2.23606797749979f;
    const float s15 = 3.872983346207417f;
    const float c33 = 2.091650066335189f;
    const float c32 = 10.246950765959598f;
    const float c31 = 1.6201851746019651f;
    const float c30 = 1.3228756555322954f;

    float yv[16];
    yv[0] = s3 * y;  yv[1] = s3 * z;  yv[2] = s3 * x;
    yv[3] = s15 * x * y;
    yv[4] = s15 * y * z;
    yv[5] = 0.5f * s5 * (3.0f * z * z - 1.0f);
    yv[6] = s15 * x * z;
    yv[7] = 0.5f * s15 * (x * x - y * y);
    yv[8]  = c33 * y * (3.0f * x * x - y * y);
    yv[9]  = c32 * x * y * z;
    yv[10] = c31 * y * (5.0f * z * z - 1.0f);
    yv[11] = c30 * z * (5.0f * z * z - 3.0f);
    yv[12] = c31 * x * (5.0f * z * z - 1.0f);
    yv[13] = 0.5f * c32 * z * (x * x - y * y);
    yv[14] = c33 * x * (x * x - 3.0f * y * y);
    yv[15] = 1.0f;

    float4* o = (float4*)(g_y + (size_t)e * 16);
    o[0] = make_float4(yv[0], yv[1], yv[2], yv[3]);
    o[1] = make_float4(yv[4], yv[5], yv[6], yv[7]);
    o[2] = make_float4(yv[8], yv[9], yv[10], yv[11]);
    o[3] = make_float4(yv[12], yv[13], yv[14], yv[15]);

    atomicAdd(&g_count[receivers[e]], 1);
}

// ---------------------------------------------------------------- CSR scan
__global__ void k_scan(int n, int E) {
    __shared__ int sums[1024];
    int t = threadIdx.x;
    int chunk = (n + 1023) >> 10;
    int b = t * chunk;
    int eidx = min(b + chunk, n);
    int s = 0;
    for (int i = b; i < eidx; i++) s += g_count[i];
    sums[t] = s;
    __syncthreads();
    for (int off = 1; off < 1024; off <<= 1) {
        int v = (t >= off) ? sums[t - off] : 0;
        __syncthreads();
        sums[t] += v;
        __syncthreads();
    }
    int pre = (t > 0) ? sums[t - 1] : 0;
    for (int i = b; i < eidx; i++) {
        g_start[i]  = pre;
        g_cursor[i] = pre;
        pre += g_count[i];
    }
    if (t == 1023) g_start[n] = E;
}

// ---------------------------------------------------------------- scatter
__global__ void k_scatter(const int* __restrict__ receivers, int E) {
    int e = blockIdx.x * blockDim.x + threadIdx.x;
    if (e >= E) return;
    int p = atomicAdd(&g_cursor[receivers[e]], 1);
    g_esort[p] = e;
}

// ---------------------------------------------------------------- radial MLP
// 2 edges per thread, 32-wide output tile: each weight LDS.128 feeds 4 FFMA2
// (2 outputs x 2 edges). h in transposed GLOBAL scratch [k][e] (coalesced,
// L2-hit, same-thread RAW). smem = weights only -> 2 blocks/SM, 16 warps.
// acc = 2x16 u64 = 64 regs -> no spills under the 128-reg cap.

__device__ __forceinline__ void passG2(const float* __restrict__ in_g, int e0, int e1,
                                       const float* __restrict__ Ws, int wstride, int j0,
                                       unsigned long long* __restrict__ acc0,
                                       unsigned long long* __restrict__ acc1) {
    #pragma unroll
    for (int q = 0; q < 16; q++) { acc0[q] = 0ULL; acc1[q] = 0ULL; }
    #pragma unroll 4
    for (int k = 0; k < 64; k++) {
        unsigned long long a = splat2(__ldg(in_g + (size_t)k * E_MAX + e0));
        unsigned long long b = splat2(__ldg(in_g + (size_t)k * E_MAX + e1));
        const ulonglong2* wp = (const ulonglong2*)(Ws + k * wstride + j0);
        #pragma unroll
        for (int q = 0; q < 8; q++) {
            ulonglong2 w = wp[q];
            fma2(acc0[2 * q],     a, w.x);
            fma2(acc0[2 * q + 1], a, w.y);
            fma2(acc1[2 * q],     b, w.x);
            fma2(acc1[2 * q + 1], b, w.y);
        }
    }
}

__device__ __forceinline__ void silu_store_g(float* __restrict__ out_g, int j0, int e,
                                             const unsigned long long* __restrict__ acc) {
    #pragma unroll
    for (int q = 0; q < 16; q++) {
        float2 v = unpack2(acc[q]);
        out_g[(size_t)(j0 + 2 * q)     * E_MAX + e] = silu(v.x);
        out_g[(size_t)(j0 + 2 * q + 1) * E_MAX + e] = silu(v.y);
    }
}

__global__ void __launch_bounds__(256, 2)
k_mlp(const float* __restrict__ radial,
      const float* __restrict__ w1, const float* __restrict__ w2,
      const float* __restrict__ w3, const float* __restrict__ w4, int E) {
    extern __shared__ float smem[];
    float* w1s = smem;                 // 512
    float* w2s = w1s + 512;            // 4096
    float* w3s = w2s + 4096;           // 4096
    float* w4s = w3s + 4096;           // 16384  (total 25088 floats = 100.4KB)

    int tid = threadIdx.x;
    for (int i = tid; i < 512;   i += 256) w1s[i] = w1[i] * 0.35355339059327379f;
    for (int i = tid; i < 4096;  i += 256) w2s[i] = w2[i] * 0.125f;
    for (int i = tid; i < 4096;  i += 256) w3s[i] = w3[i] * 0.125f;
    for (int i = tid; i < 16384; i += 256) w4s[i] = w4[i] * 0.125f;
    __syncthreads();

    int base = blockIdx.x * 512;
    int e0 = base + tid;
    int e1 = base + 256 + tid;
    if (e0 >= E) return;
    int eB = min(e1, E - 1);   // duplicate writes of edge E-1 are value-identical -> benign

    unsigned long long acc0[16], acc1[16];

    // ---- layer 1: 8 -> 64 -> g_hA (2 j-tiles of 32)
    {
        const float4* rp0 = (const float4*)(radial + (size_t)e0 * 8);
        const float4* rp1 = (const float4*)(radial + (size_t)eB * 8);
        float4 a0 = __ldg(rp0), a1 = __ldg(rp0 + 1);
        float4 b0 = __ldg(rp1), b1 = __ldg(rp1 + 1);
        float r0[8] = {a0.x, a0.y, a0.z, a0.w, a1.x, a1.y, a1.z, a1.w};
        float r1[8] = {b0.x, b0.y, b0.z, b0.w, b1.x, b1.y, b1.z, b1.w};
        #pragma unroll
        for (int t = 0; t < 2; t++) {
            int j0 = t * 32;
            #pragma unroll
            for (int q = 0; q < 16; q++) { acc0[q] = 0ULL; acc1[q] = 0ULL; }
            #pragma unroll
            for (int k = 0; k < 8; k++) {
                unsigned long long a = splat2(r0[k]);
                unsigned long long b = splat2(r1[k]);
                const ulonglong2* wp = (const ulonglong2*)(w1s + k * 64 + j0);
                #pragma unroll
                for (int q = 0; q < 8; q++) {
                    ulonglong2 w = wp[q];
                    fma2(acc0[2 * q],     a, w.x);
                    fma2(acc0[2 * q + 1], a, w.y);
                    fma2(acc1[2 * q],     b, w.x);
                    fma2(acc1[2 * q + 1], b, w.y);
                }
            }
            silu_store_g(g_hA, j0, e0, acc0);
            silu_store_g(g_hA, j0, eB, acc1);
        }
    }

    // ---- layer 2: g_hA -> g_hB (2 j-tiles of 32)
    #pragma unroll 1
    for (int t = 0; t < 2; t++) {
        int j0 = t * 32;
        passG2(g_hA, e0, eB, w2s, 64, j0, acc0, acc1);
        silu_store_g(g_hB, j0, e0, acc0);
        silu_store_g(g_hB, j0, eB, acc1);
    }

    // ---- layer 3: g_hB -> g_hA (2 j-tiles of 32)
    #pragma unroll 1
    for (int t = 0; t < 2; t++) {
        int j0 = t * 32;
        passG2(g_hB, e0, eB, w3s, 64, j0, acc0, acc1);
        silu_store_g(g_hA, j0, e0, acc0);
        silu_store_g(g_hA, j0, eB, acc1);
    }

    // ---- layer 4: g_hA -> g_mix (8 j-tiles of 32, no activation)
    float* mo0 = g_mix + (size_t)e0 * 256;
    float* mo1 = g_mix + (size_t)e1 * 256;
    #pragma unroll 1
    for (int t = 0; t < 8; t++) {
        int j0 = t * 32;
        passG2(g_hA, e0, eB, w4s, 256, j0, acc0, acc1);
        // packed u64 pairs are exactly two consecutive floats -> direct stores
        {
            ulonglong2* op = (ulonglong2*)(mo0 + j0);
            #pragma unroll
            for (int q = 0; q < 8; q++)
                op[q] = make_ulonglong2(acc0[2 * q], acc0[2 * q + 1]);
        }
        if (e1 < E) {
            ulonglong2* op = (ulonglong2*)(mo1 + j0);
            #pragma unroll
            for (int q = 0; q < 8; q++)
                op[q] = make_ulonglong2(acc1[2 * q], acc1[2 * q + 1]);
        }
    }
}

// --------------------------------------------------- gather-side reduction
__global__ void __launch_bounds__(256)
k_out(const float* __restrict__ node_feats, const int* __restrict__ senders,
      float* __restrict__ out, int N) {
    __shared__ float red[8 * 1024];
    int node = blockIdx.x;
    int tid = threadIdx.x;
    int w = tid >> 5, lane = tid & 31;
    int beg = g_start[node], end = g_start[node + 1];

    float acc[32];
    #pragma unroll
    for (int i = 0; i < 32; i++) acc[i] = 0.0f;

    for (int p = beg + w; p < end; p += 8) {
        int e = g_esort[p];
        int snd = senders[e];
        const float* mixp = g_mix + (size_t)e * 256;
        const float4* yp = (const float4*)(g_y + (size_t)e * 16);
        float4 ya = __ldg(yp), yb = __ldg(yp + 1), yc = __ldg(yp + 2), yd = __ldg(yp + 3);
        float yv[15] = {ya.x, ya.y, ya.z, ya.w, yb.x, yb.y, yb.z, yb.w,
                        yc.x, yc.y, yc.z, yc.w, yd.x, yd.y, yd.z};
        #pragma unroll
        for (int h = 0; h < 2; h++) {
            int c = lane + 32 * h;
            float s   = __ldg(node_feats + (size_t)snd * 64 + c);
            float sm0 = s * __ldg(mixp + c);
            float sm1 = s * __ldg(mixp + 64 + c);
            float sm2 = s * __ldg(mixp + 128 + c);
            float sm3 = s * __ldg(mixp + 192 + c);
            float* a = acc + 16 * h;
            a[0] += sm0;
            a[1] = fmaf(sm1, yv[0], a[1]);
            a[2] = fmaf(sm1, yv[1], a[2]);
            a[3] = fmaf(sm1, yv[2], a[3]);
            #pragma unroll
            for (int m = 0; m < 5; m++) a[4 + m] = fmaf(sm2, yv[3 + m], a[4 + m]);
            #pragma unroll
            for (int m = 0; m < 7; m++) a[9 + m] = fmaf(sm3, yv[8 + m], a[9 + m]);
        }
    }

    float* rw = red + w * 1024;
    #pragma unroll
    for (int h = 0; h < 2; h++) {
        int c = lane + 32 * h;
        float* a = acc + 16 * h;
        rw[c] = a[0];
        rw[64 + c * 3 + 0] = a[1];
        rw[64 + c * 3 + 1] = a[2];
        rw[64 + c * 3 + 2] = a[3];
        #pragma unroll
        for (int m = 0; m < 5; m++) rw[256 + c * 5 + m] = a[4 + m];
        #pragma unroll
        for (int m = 0; m < 7; m++) rw[576 + c * 7 + m] = a[9 + m];
    }
    __syncthreads();

    float* outp = out + (size_t)node * 1024;
    #pragma unroll
    for (int i = 0; i < 4; i++) {
        int o = tid + 256 * i;
        float sum = 0.0f;
        #pragma unroll
        for (int ww = 0; ww < 8; ww++) sum += red[ww * 1024 + o];
        outp[o] = sum * 0.25f;   // 1/sqrt(16)
    }
}

// ---------------------------------------------------------------- launcher
extern "C" void kernel_launch(void* const* d_in, const int* in_sizes, int n_in,
                              void* d_out, int out_size) {
    const float* vectors    = (const float*)d_in[0];
    const float* node_feats = (const float*)d_in[1];
    const float* radial     = (const float*)d_in[2];
    const float* w1         = (const float*)d_in[3];
    const float* w2         = (const float*)d_in[4];
    const float* w3         = (const float*)d_in[5];
    const float* w4         = (const float*)d_in[6];
    const int*   senders    = (const int*)d_in[7];
    const int*   receivers  = (const int*)d_in[8];

    int E = in_sizes[7];
    int N = in_sizes[1] / 64;

    const int SMEM_MLP = 25088 * 4;   // weights only: 100,352 B -> 2 blocks/SM
    cudaFuncSetAttribute(k_mlp, cudaFuncAttributeMaxDynamicSharedMemorySize, SMEM_MLP);

    int gE = (E + 255) / 256;
    int gM = (E + 511) / 512;
    k_zero<<<(N + 1 + 255) / 256, 256>>>(N);
    k_y_hist<<<gE, 256>>>(vectors, receivers, E);
    k_scan<<<1, 1024>>>(N, E);
    k_mlp<<<gM, 256, SMEM_MLP>>>(radial, w1, w2, w3, w4, E);
    k_scatter<<<gE, 256>>>(receivers, E);
    k_out<<<N, 256>>>(node_feats, senders, (float*)d_out, N);
}